// round 16
// baseline (speedup 1.0000x reference)
#include <cuda_runtime.h>
#include <cuda_fp16.h>

#define BSZ   16
#define TSEQ  2048
#define NDIM  32
#define NH    4
#define HS    8
#define NS    4               // key-split chunks (8 tiles of 64 = 512 keys)
#define QS_N  64              // 32-query strips

// Scratch (device globals — no allocation allowed)
__device__ unsigned g_Q2[BSZ*NH*TSEQ*HS];   // tf32 pairs: [tok][j] = (d=j, d=j+4), pre-scaled
__device__ unsigned g_K2[BSZ*NH*TSEQ*HS];   // tf32 pairs
__device__ __half   g_Vt[BSZ*NH*HS*TSEQ];   // f16, [b][h][d][tok]
__device__ float    g_Apart[NS*BSZ*TSEQ*NDIM];
__device__ float    g_Lpart[NS*BSZ*TSEQ*NH];

typedef unsigned u32;
typedef unsigned long long u64;

__device__ __forceinline__ u32 to_tf32(float x){
    u32 r; asm("cvt.rna.tf32.f32 %0,%1;":"=r"(r):"f"(x)); return r;
}
__device__ __forceinline__ float fast_ex2(float x){
    float r; asm("ex2.approx.ftz.f32 %0,%1;":"=f"(r):"f"(x)); return r;
}
__device__ __forceinline__ u64 f2_pack(float lo, float hi){
    u64 r; asm("mov.b64 %0,{%1,%2};":"=l"(r):"f"(lo),"f"(hi)); return r;
}
__device__ __forceinline__ void f2_unpack(u64 v, float& lo, float& hi){
    asm("mov.b64 {%0,%1},%2;":"=f"(lo),"=f"(hi):"l"(v));
}
__device__ __forceinline__ u64 f2_fma(u64 a, u64 b, u64 c){
    u64 d; asm("fma.rn.f32x2 %0,%1,%2,%3;":"=l"(d):"l"(a),"l"(b),"l"(c)); return d;
}
// pack(lo,hi): d.lo = lo, d.hi = hi  (cvt packs first source into UPPER half)
__device__ __forceinline__ u32 pack_h2(float lo, float hi){
    u32 r; asm("cvt.rn.f16x2.f32 %0, %1, %2;" : "=r"(r) : "f"(hi), "f"(lo)); return r;
}
// D(16x8,f32) = A(16x8,tf32) * B(8x8,tf32), C = 0
__device__ __forceinline__ void mma_qk(float* d, const u32* a, u32 b0, u32 b1){
    asm("mma.sync.aligned.m16n8k8.row.col.f32.tf32.tf32.f32 "
        "{%0,%1,%2,%3},{%4,%5,%6,%7},{%8,%9},{%10,%11,%12,%13};"
        : "=f"(d[0]),"=f"(d[1]),"=f"(d[2]),"=f"(d[3])
        : "r"(a[0]),"r"(a[1]),"r"(a[2]),"r"(a[3]), "r"(b0),"r"(b1),
          "f"(0.f),"f"(0.f),"f"(0.f),"f"(0.f));
}
// D(16x8,f32) += A(16x16,f16) * B(16x8,f16)
__device__ __forceinline__ void mma_pv(float* d, u32 a0,u32 a1,u32 a2,u32 a3, u32 b0,u32 b1){
    asm("mma.sync.aligned.m16n8k16.row.col.f32.f16.f16.f32 "
        "{%0,%1,%2,%3},{%4,%5,%6,%7},{%8,%9},{%0,%1,%2,%3};"
        : "+f"(d[0]),"+f"(d[1]),"+f"(d[2]),"+f"(d[3])
        : "r"(a0),"r"(a1),"r"(a2),"r"(a3), "r"(b0),"r"(b1));
}

// ---------------------------------------------------------------------------
// Kernel 1: QKV projection, m-split + f32x2-packed FMA.
// grid=(256, 3), block=128. blockIdx.y = matrix m. Thread = token.
// W staged in smem as (d,d+1) u64 pairs -> each FFMA2 does 2 output dims.
// ---------------------------------------------------------------------------
__global__ __launch_bounds__(128) void qkv_kernel(
    const float* __restrict__ x,
    const float* __restrict__ Wq, const float* __restrict__ bq,
    const float* __restrict__ Wk, const float* __restrict__ bk,
    const float* __restrict__ Wv, const float* __restrict__ bv)
{
    __shared__ u64   sW2[16*32];   // [dp][c] = (W[2dp][c], W[2dp+1][c])  4KB
    __shared__ float sB[32];
    int m   = blockIdx.y;
    int tid = threadIdx.x;
    const float* W  = (m == 0) ? Wq : (m == 1) ? Wk : Wv;
    const float* bb = (m == 0) ? bq : (m == 1) ? bk : bv;
#pragma unroll
    for (int i = tid; i < 512; i += 128) {
        int dp = i >> 5, c = i & 31;
        sW2[i] = f2_pack(W[(2*dp)*32 + c], W[(2*dp+1)*32 + c]);
    }
    if (tid < 32) sB[tid] = bb[tid];
    __syncthreads();

    int tok = blockIdx.x * 128 + tid;
    int b = tok >> 11;
    int t = tok & (TSEQ - 1);

    u64 xv2[32];   // duplicated-pack x
    {
        const float4* xr = (const float4*)(x + (size_t)tok * NDIM);
#pragma unroll
        for (int i = 0; i < 8; i++) {
            float4 v = xr[i];
            xv2[4*i  ] = f2_pack(v.x, v.x);
            xv2[4*i+1] = f2_pack(v.y, v.y);
            xv2[4*i+2] = f2_pack(v.z, v.z);
            xv2[4*i+3] = f2_pack(v.w, v.w);
        }
    }

    u64 acc2[16];
#pragma unroll
    for (int dp = 0; dp < 16; dp++) acc2[dp] = f2_pack(sB[2*dp], sB[2*dp+1]);
#pragma unroll
    for (int dp = 0; dp < 16; dp++) {
        const ulonglong2* wp = (const ulonglong2*)&sW2[dp*32];
#pragma unroll
        for (int cc = 0; cc < 16; cc++) {
            ulonglong2 w = wp[cc];
            acc2[dp] = f2_fma(xv2[2*cc  ], w.x, acc2[dp]);
            acc2[dp] = f2_fma(xv2[2*cc+1], w.y, acc2[dp]);
        }
    }
    float out[32];
#pragma unroll
    for (int dp = 0; dp < 16; dp++) f2_unpack(acc2[dp], out[2*dp], out[2*dp+1]);

    const float SC = 0.35355339059327f * 1.44269504088896f; // 1/sqrt(8)*log2(e)
    if (m == 0) {
#pragma unroll
        for (int h = 0; h < NH; h++) {
            size_t tb = ((size_t)(b*NH + h)) * TSEQ + t;
#pragma unroll
            for (int j = 0; j < 4; j++)
                *(uint2*)&g_Q2[tb*8 + j*2] =
                    make_uint2(to_tf32(out[h*8+j]*SC), to_tf32(out[h*8+j+4]*SC));
        }
    } else if (m == 1) {
#pragma unroll
        for (int h = 0; h < NH; h++) {
            size_t tb = ((size_t)(b*NH + h)) * TSEQ + t;
#pragma unroll
            for (int j = 0; j < 4; j++)
                *(uint2*)&g_K2[tb*8 + j*2] =
                    make_uint2(to_tf32(out[h*8+j]), to_tf32(out[h*8+j+4]));
        }
    } else {
#pragma unroll
        for (int d = 0; d < 32; d++) {
            int h = d >> 3, dd = d & 7;
            g_Vt[(((size_t)(b*NH+h))*HS + dd)*TSEQ + t] = __float2half_rn(out[d]);
        }
    }
}

// ---------------------------------------------------------------------------
// Kernel 2: causal attention, tensor cores, split-K, K-prefetch pipeline.
// grid=(NS, QS_N, BSZ), block=128 (4 warps). Warp = head; strip = 32 queries.
// Next tile's K fragments are loaded between grp0 and grp1 of the current
// tile so the tile-head LDG->MMA stall is hidden under MUFU/MMA work.
// ---------------------------------------------------------------------------
__global__ __launch_bounds__(128, 4) void attn_kernel()
{
    int s   = blockIdx.x;
    int qh  = (QS_N - 1) - (int)blockIdx.y;   // heavy strips first
    int b   = blockIdx.z;
    int ktd = qh >> 1;                        // diagonal 64-key tile
    if (8*s > ktd) return;

    int h    = threadIdx.x >> 5;              // warp = head
    int lane = threadIdx.x & 31;
    int g    = lane >> 2;                     // row within fragment group
    int t    = lane & 3;                      // thread-in-quad
    int q0   = qh * 32;

    const u32*    Qp = g_Q2 + ((size_t)(b*NH + h))*TSEQ*8;
    const u32*    Kp = g_K2 + ((size_t)(b*NH + h))*TSEQ*8;
    const __half* Vp = g_Vt + ((size_t)(b*NH + h))*HS*TSEQ;

    // Q fragments: 2 row-groups of 16
    u32 qa[2][4];
#pragma unroll
    for (int grp = 0; grp < 2; grp++) {
        uint2 lo = *(const uint2*)&Qp[(size_t)(q0 + 16*grp +     g)*8 + t*2];
        uint2 hi = *(const uint2*)&Qp[(size_t)(q0 + 16*grp + 8 + g)*8 + t*2];
        qa[grp][0] = lo.x; qa[grp][2] = lo.y;
        qa[grp][1] = hi.x; qa[grp][3] = hi.y;
    }

    float z[2][4] = {{0.f,0.f,0.f,0.f},{0.f,0.f,0.f,0.f}};
    float l4[4]   = {0.f,0.f,0.f,0.f};

    int kt0 = 8*s;
    int kt1 = 8*s + 7; if (kt1 > ktd) kt1 = ktd;

    // preload K fragments for first tile
    u32 kb0[8], kb1[8];
#pragma unroll
    for (int c = 0; c < 8; c++) {
        uint2 kk = *(const uint2*)&Kp[(size_t)(kt0*64 + 8*c + g)*8 + t*2];
        kb0[c] = kk.x; kb1[c] = kk.y;
    }

#define GRP_BODY(GRP, DIAG)                                                    \
    {                                                                          \
        int r0 = q0 + 16*(GRP) + g;                                            \
        float p[8][4];                                                         \
        _Pragma("unroll")                                                      \
        for (int c = 0; c < 8; c++) mma_qk(p[c], qa[GRP], kb0[c], kb1[c]);     \
        _Pragma("unroll")                                                      \
        for (int c = 0; c < 8; c++) {                                          \
            int col = j0 + 8*c + 2*t;                                          \
            float e0, e1, e2, e3;                                              \
            if (DIAG) {                                                        \
                e0 = (col   <= r0  ) ? fast_ex2(p[c][0]) : 0.f;                \
                e1 = (col+1 <= r0  ) ? fast_ex2(p[c][1]) : 0.f;                \
                e2 = (col   <= r0+8) ? fast_ex2(p[c][2]) : 0.f;                \
                e3 = (col+1 <= r0+8) ? fast_ex2(p[c][3]) : 0.f;                \
            } else {                                                           \
                e0 = fast_ex2(p[c][0]); e1 = fast_ex2(p[c][1]);                \
                e2 = fast_ex2(p[c][2]); e3 = fast_ex2(p[c][3]);                \
            }                                                                  \
            p[c][0] = e0; p[c][1] = e1; p[c][2] = e2; p[c][3] = e3;            \
            l4[2*(GRP)+0] += e0 + e1;                                          \
            l4[2*(GRP)+1] += e2 + e3;                                          \
        }                                                                      \
        _Pragma("unroll")                                                      \
        for (int cc = 0; cc < 4; cc++) {                                       \
            u32 a0 = pack_h2(p[2*cc  ][0], p[2*cc  ][1]);                      \
            u32 a1 = pack_h2(p[2*cc  ][2], p[2*cc  ][3]);                      \
            u32 a2 = pack_h2(p[2*cc+1][0], p[2*cc+1][1]);                      \
            u32 a3 = pack_h2(p[2*cc+1][2], p[2*cc+1][3]);                      \
            mma_pv(z[GRP], a0, a1, a2, a3, vb0[cc], vb1[cc]);                  \
        }                                                                      \
    }

    for (int kt = kt0; kt <= kt1; kt++) {
        int j0 = kt*64;
        // V fragments (early issue; consumed after QK+EX2, latency hidden)
        u32 vb0[4], vb1[4];
#pragma unroll
        for (int cc = 0; cc < 4; cc++) {
            const __half* vrow = Vp + (size_t)g*TSEQ + j0 + 16*cc;
            vb0[cc] = *(const u32*)(vrow + 2*t);
            vb1[cc] = *(const u32*)(vrow + 8 + 2*t);
        }
        bool diag = (kt == ktd);
        bool pf   = (kt < kt1);

        if (diag) { GRP_BODY(0, true) } else { GRP_BODY(0, false) }

        // prefetch next tile's K fragments under grp1's compute
        u32 nk0[8], nk1[8];
        if (pf) {
            int jn = (kt+1)*64;
#pragma unroll
            for (int c = 0; c < 8; c++) {
                uint2 kk = *(const uint2*)&Kp[(size_t)(jn + 8*c + g)*8 + t*2];
                nk0[c] = kk.x; nk1[c] = kk.y;
            }
        }

        if (diag) { GRP_BODY(1, true) } else { GRP_BODY(1, false) }

        if (pf) {
#pragma unroll
            for (int c = 0; c < 8; c++) { kb0[c] = nk0[c]; kb1[c] = nk1[c]; }
        }
    }
#undef GRP_BODY

    // epilogue: quad-reduce l, store partials
#pragma unroll
    for (int grp = 0; grp < 2; grp++) {
#pragma unroll
        for (int rr = 0; rr < 2; rr++) {
            float ls = l4[2*grp + rr];
            ls += __shfl_xor_sync(0xffffffffu, ls, 1);
            ls += __shfl_xor_sync(0xffffffffu, ls, 2);
            int row = q0 + 16*grp + 8*rr + g;
            size_t base = ((size_t)s*BSZ + b)*TSEQ + row;
            *(float2*)&g_Apart[base*NDIM + h*HS + 2*t] =
                make_float2(z[grp][2*rr], z[grp][2*rr+1]);
            if (t == 0) g_Lpart[base*NH + h] = ls;
        }
    }
}

// ---------------------------------------------------------------------------
// Kernel 3: merge split-K partials + normalize + output projection.
// grid = (128, 2); blockIdx.y picks 16 output dims. One thread per token.
// ---------------------------------------------------------------------------
__global__ __launch_bounds__(256) void proj_kernel(
    const float* __restrict__ Wp, const float* __restrict__ bp,
    float* __restrict__ out)
{
    __shared__ float4 sW[128];
    __shared__ float  sB[16];
    int tid  = threadIdx.x;
    int half = blockIdx.y;
    if (tid < 128) sW[tid] = ((const float4*)Wp)[half*128 + tid];
    if (tid < 16)  sB[tid] = bp[half*16 + tid];
    __syncthreads();

    int tok = blockIdx.x * 256 + tid;
    int b = tok >> 11;
    int t = tok & (TSEQ - 1);
    int nS = (t >> 9) + 1;

    float av[32];
    float lv[4];
#pragma unroll
    for (int i = 0; i < 32; i++) av[i] = 0.f;
#pragma unroll
    for (int h = 0; h < 4; h++) lv[h] = 0.f;

    for (int sI = 0; sI < nS; sI++) {
        size_t base = (((size_t)sI*BSZ + b) * TSEQ + t);
        const float4* ap = (const float4*)&g_Apart[base * NDIM];
#pragma unroll
        for (int i = 0; i < 8; i++) {
            float4 v = ap[i];
            av[4*i] += v.x; av[4*i+1] += v.y; av[4*i+2] += v.z; av[4*i+3] += v.w;
        }
        const float4 lp = *(const float4*)&g_Lpart[base * NH];
        lv[0] += lp.x; lv[1] += lp.y; lv[2] += lp.z; lv[3] += lp.w;
    }

    float zv[32];
#pragma unroll
    for (int h = 0; h < 4; h++) {
        float inv = __frcp_rn(lv[h]);
#pragma unroll
        for (int d = 0; d < 8; d++) zv[h*8+d] = av[h*8+d] * inv;
    }

    float o[16];
#pragma unroll
    for (int d = 0; d < 16; d++) {
        float acc = sB[d];
#pragma unroll
        for (int c = 0; c < 8; c++) {
            float4 w = sW[d*8 + c];
            acc = fmaf(zv[4*c],   w.x,
                  fmaf(zv[4*c+1], w.y,
                  fmaf(zv[4*c+2], w.z,
                  fmaf(zv[4*c+3], w.w, acc))));
        }
        o[d] = acc;
    }
    float4* op = (float4*)&out[(size_t)tok * NDIM + half*16];
#pragma unroll
    for (int c = 0; c < 4; c++)
        op[c] = make_float4(o[4*c], o[4*c+1], o[4*c+2], o[4*c+3]);
}

// ---------------------------------------------------------------------------
extern "C" void kernel_launch(void* const* d_in, const int* in_sizes, int n_in,
                              void* d_out, int out_size)
{
    const float* x  = (const float*)d_in[0];
    const float* Wq = (const float*)d_in[1];
    const float* bq = (const float*)d_in[2];
    const float* Wk = (const float*)d_in[3];
    const float* bk = (const float*)d_in[4];
    const float* Wv = (const float*)d_in[5];
    const float* bv = (const float*)d_in[6];
    const float* Wp = (const float*)d_in[7];
    const float* bp = (const float*)d_in[8];
    float* out = (float*)d_out;

    qkv_kernel<<<dim3((BSZ*TSEQ)/128, 3), 128>>>(x, Wq, bq, Wk, bk, Wv, bv);
    attn_kernel<<<dim3(NS, QS_N, BSZ), 128>>>();
    proj_kernel<<<dim3((BSZ*TSEQ)/256, 2), 256>>>(Wp, bp, out);
}

// round 17
// speedup vs baseline: 1.3820x; 1.3820x over previous
#include <cuda_runtime.h>
#include <cuda_fp16.h>

#define BSZ   16
#define TSEQ  2048
#define NDIM  32
#define NH    4
#define HS    8
#define NS    4               // key-split chunks (8 tiles of 64 = 512 keys)
#define QB_N  (TSEQ/64)       // 32 query bands of 64

// Scratch (device globals — no allocation allowed)
__device__ unsigned g_Q2[BSZ*NH*TSEQ*HS];   // tf32 pairs: [tok][j] = (d=j, d=j+4), pre-scaled
__device__ unsigned g_K2[BSZ*NH*TSEQ*HS];   // tf32 pairs
__device__ __half   g_Vt[BSZ*NH*HS*TSEQ];   // f16, [b][h][d][tok]
__device__ float    g_Apart[NS*BSZ*TSEQ*NDIM];
__device__ float    g_Lpart[NS*BSZ*TSEQ*NH];

typedef unsigned u32;

__device__ __forceinline__ u32 to_tf32(float x){
    u32 r; asm("cvt.rna.tf32.f32 %0,%1;":"=r"(r):"f"(x)); return r;
}
__device__ __forceinline__ float fast_ex2(float x){
    float r; asm("ex2.approx.ftz.f32 %0,%1;":"=f"(r):"f"(x)); return r;
}
// pack(lo,hi): d.lo = lo, d.hi = hi  (cvt packs first source into UPPER half)
__device__ __forceinline__ u32 pack_h2(float lo, float hi){
    u32 r; asm("cvt.rn.f16x2.f32 %0, %1, %2;" : "=r"(r) : "f"(hi), "f"(lo)); return r;
}
// D(16x8,f32) = A(16x8,tf32) * B(8x8,tf32), C = 0
__device__ __forceinline__ void mma_qk(float* d, const u32* a, u32 b0, u32 b1){
    asm("mma.sync.aligned.m16n8k8.row.col.f32.tf32.tf32.f32 "
        "{%0,%1,%2,%3},{%4,%5,%6,%7},{%8,%9},{%10,%11,%12,%13};"
        : "=f"(d[0]),"=f"(d[1]),"=f"(d[2]),"=f"(d[3])
        : "r"(a[0]),"r"(a[1]),"r"(a[2]),"r"(a[3]), "r"(b0),"r"(b1),
          "f"(0.f),"f"(0.f),"f"(0.f),"f"(0.f));
}
// D(16x8,f32) += A(16x16,f16) * B(16x8,f16)
__device__ __forceinline__ void mma_pv(float* d, u32 a0,u32 a1,u32 a2,u32 a3, u32 b0,u32 b1){
    asm("mma.sync.aligned.m16n8k16.row.col.f32.f16.f16.f32 "
        "{%0,%1,%2,%3},{%4,%5,%6,%7},{%8,%9},{%0,%1,%2,%3};"
        : "+f"(d[0]),"+f"(d[1]),"+f"(d[2]),"+f"(d[3])
        : "r"(a0),"r"(a1),"r"(a2),"r"(a3), "r"(b0),"r"(b1));
}

// ---------------------------------------------------------------------------
// Kernel 1: fused QKV projection. grid=256, block=128 (same per-thread code
// as the 73.8us round-11 version; repartitioned so grid >= SM count).
// One thread per token, computes all 96 outputs; x loaded from global ONCE.
// ---------------------------------------------------------------------------
__global__ __launch_bounds__(128) void qkv_kernel(
    const float* __restrict__ x,
    const float* __restrict__ Wq, const float* __restrict__ bq,
    const float* __restrict__ Wk, const float* __restrict__ bk,
    const float* __restrict__ Wv, const float* __restrict__ bv)
{
    __shared__ float4 sW[3*256];   // 3 matrices of 32x32 floats
    __shared__ float  sB[96];
    int tid = threadIdx.x;
#pragma unroll
    for (int i = tid; i < 256; i += 128) {
        sW[i]       = ((const float4*)Wq)[i];
        sW[256+i]   = ((const float4*)Wk)[i];
        sW[512+i]   = ((const float4*)Wv)[i];
    }
    if (tid < 96) sB[tid] = (tid < 32) ? bq[tid] : (tid < 64 ? bk[tid-32] : bv[tid-64]);
    __syncthreads();

    int tok = blockIdx.x * 128 + tid;
    int b = tok >> 11;
    int t = tok & (TSEQ - 1);

    float xv[32];
    const float4* xr = (const float4*)(x + (size_t)tok * NDIM);
#pragma unroll
    for (int i = 0; i < 8; i++) {
        float4 v = xr[i];
        xv[4*i] = v.x; xv[4*i+1] = v.y; xv[4*i+2] = v.z; xv[4*i+3] = v.w;
    }

    const float SC = 0.35355339059327f * 1.44269504088896f; // 1/sqrt(8)*log2(e)

#pragma unroll
    for (int m = 0; m < 3; m++) {
        float out[32];
#pragma unroll
        for (int d = 0; d < 32; d++) {
            float acc = sB[m*32 + d];
#pragma unroll
            for (int c = 0; c < 8; c++) {
                float4 w = sW[m*256 + d*8 + c];
                acc = fmaf(xv[4*c],   w.x,
                      fmaf(xv[4*c+1], w.y,
                      fmaf(xv[4*c+2], w.z,
                      fmaf(xv[4*c+3], w.w, acc))));
            }
            out[d] = acc;
        }

        if (m == 0) {
#pragma unroll
            for (int h = 0; h < NH; h++) {
                size_t tb = ((size_t)(b*NH + h)) * TSEQ + t;
#pragma unroll
                for (int j = 0; j < 4; j++)
                    *(uint2*)&g_Q2[tb*8 + j*2] =
                        make_uint2(to_tf32(out[h*8+j]*SC), to_tf32(out[h*8+j+4]*SC));
            }
        } else if (m == 1) {
#pragma unroll
            for (int h = 0; h < NH; h++) {
                size_t tb = ((size_t)(b*NH + h)) * TSEQ + t;
#pragma unroll
                for (int j = 0; j < 4; j++)
                    *(uint2*)&g_K2[tb*8 + j*2] =
                        make_uint2(to_tf32(out[h*8+j]), to_tf32(out[h*8+j+4]));
            }
        } else {
#pragma unroll
            for (int d = 0; d < 32; d++) {
                int h = d >> 3, dd = d & 7;
                g_Vt[(((size_t)(b*NH+h))*HS + dd)*TSEQ + t] = __float2half_rn(out[d]);
            }
        }
    }
}

// ---------------------------------------------------------------------------
// Kernel 2: causal attention on tensor cores, split-K, no smem, no syncs.
// grid=(NS, QB_N, BSZ), block=256 (8 warps). Warp = (head h, 32-query sub).
// Per 64-key tile: 16x tf32 m16n8k8 (QK), f32 exp2 on D frags, f16x2 pack,
// 8x f16 m16n8k16 (PV). Partials (sum p*v, sum p) -> g_Apart/g_Lpart.
// (Byte-identical to the 73.8us round-11 version.)
// ---------------------------------------------------------------------------
__global__ __launch_bounds__(256) void attn_kernel()
{
    int s  = blockIdx.x;
    int qb = (QB_N - 1) - (int)blockIdx.y;   // heavy bands first
    int b  = blockIdx.z;
    if (8*s > qb) return;

    int wid  = threadIdx.x >> 5;
    int lane = threadIdx.x & 31;
    int h    = wid & 3;
    int sub  = wid >> 2;
    int g    = lane >> 2;     // groupID (row within fragment)
    int t    = lane & 3;      // thread-in-quad
    int q0   = qb*64 + sub*32;

    const u32*    Qp = g_Q2 + ((size_t)(b*NH + h))*TSEQ*8;
    const u32*    Kp = g_K2 + ((size_t)(b*NH + h))*TSEQ*8;
    const __half* Vp = g_Vt + ((size_t)(b*NH + h))*HS*TSEQ;

    // Q fragments: 2 row-groups of 16
    u32 qa[2][4];
#pragma unroll
    for (int grp = 0; grp < 2; grp++) {
        uint2 lo = *(const uint2*)&Qp[(size_t)(q0 + 16*grp +     g)*8 + t*2];
        uint2 hi = *(const uint2*)&Qp[(size_t)(q0 + 16*grp + 8 + g)*8 + t*2];
        qa[grp][0] = lo.x; qa[grp][2] = lo.y;
        qa[grp][1] = hi.x; qa[grp][3] = hi.y;
    }

    float z[2][4] = {{0.f,0.f,0.f,0.f},{0.f,0.f,0.f,0.f}};
    float l4[4]   = {0.f,0.f,0.f,0.f};

    int ktd = qb;
    int kt1 = 8*s + 7; if (kt1 > ktd) kt1 = ktd;

    for (int kt = 8*s; kt <= kt1; kt++) {
        int j0 = kt*64;
        // K B-fragments: 8 chunks of 8 keys
        u32 kb0[8], kb1[8];
#pragma unroll
        for (int c = 0; c < 8; c++) {
            uint2 kk = *(const uint2*)&Kp[(size_t)(j0 + 8*c + g)*8 + t*2];
            kb0[c] = kk.x; kb1[c] = kk.y;
        }
        // V B-fragments: 4 chunks of 16 keys
        u32 vb0[4], vb1[4];
#pragma unroll
        for (int cc = 0; cc < 4; cc++) {
            const __half* vrow = Vp + (size_t)g*TSEQ + j0 + 16*cc;
            vb0[cc] = *(const u32*)(vrow + 2*t);
            vb1[cc] = *(const u32*)(vrow + 8 + 2*t);
        }
        bool diag = (kt == ktd);

#pragma unroll
        for (int grp = 0; grp < 2; grp++) {
            int r0 = q0 + 16*grp + g;
            float p[8][4];
#pragma unroll
            for (int c = 0; c < 8; c++) mma_qk(p[c], qa[grp], kb0[c], kb1[c]);
#pragma unroll
            for (int c = 0; c < 8; c++) {
                int col = j0 + 8*c + 2*t;
                float e0, e1, e2, e3;
                if (diag) {
                    e0 = (col   <= r0  ) ? fast_ex2(p[c][0]) : 0.f;
                    e1 = (col+1 <= r0  ) ? fast_ex2(p[c][1]) : 0.f;
                    e2 = (col   <= r0+8) ? fast_ex2(p[c][2]) : 0.f;
                    e3 = (col+1 <= r0+8) ? fast_ex2(p[c][3]) : 0.f;
                } else {
                    e0 = fast_ex2(p[c][0]); e1 = fast_ex2(p[c][1]);
                    e2 = fast_ex2(p[c][2]); e3 = fast_ex2(p[c][3]);
                }
                p[c][0] = e0; p[c][1] = e1; p[c][2] = e2; p[c][3] = e3;
                l4[2*grp+0] += e0 + e1;
                l4[2*grp+1] += e2 + e3;
            }
#pragma unroll
            for (int cc = 0; cc < 4; cc++) {
                u32 a0 = pack_h2(p[2*cc  ][0], p[2*cc  ][1]);
                u32 a1 = pack_h2(p[2*cc  ][2], p[2*cc  ][3]);
                u32 a2 = pack_h2(p[2*cc+1][0], p[2*cc+1][1]);
                u32 a3 = pack_h2(p[2*cc+1][2], p[2*cc+1][3]);
                mma_pv(z[grp], a0, a1, a2, a3, vb0[cc], vb1[cc]);
            }
        }
    }

    // epilogue: quad-reduce l, store partials
#pragma unroll
    for (int grp = 0; grp < 2; grp++) {
#pragma unroll
        for (int rr = 0; rr < 2; rr++) {
            float ls = l4[2*grp + rr];
            ls += __shfl_xor_sync(0xffffffffu, ls, 1);
            ls += __shfl_xor_sync(0xffffffffu, ls, 2);
            int row = q0 + 16*grp + 8*rr + g;
            size_t base = ((size_t)s*BSZ + b)*TSEQ + row;
            *(float2*)&g_Apart[base*NDIM + h*HS + 2*t] =
                make_float2(z[grp][2*rr], z[grp][2*rr+1]);
            if (t == 0) g_Lpart[base*NH + h] = ls;
        }
    }
}

// ---------------------------------------------------------------------------
// Kernel 3: merge split-K partials + normalize + output projection.
// grid = (128, 2); blockIdx.y picks 16 output dims. One thread per token.
// ---------------------------------------------------------------------------
__global__ __launch_bounds__(256) void proj_kernel(
    const float* __restrict__ Wp, const float* __restrict__ bp,
    float* __restrict__ out)
{
    __shared__ float4 sW[128];
    __shared__ float  sB[16];
    int tid  = threadIdx.x;
    int half = blockIdx.y;
    if (tid < 128) sW[tid] = ((const float4*)Wp)[half*128 + tid];
    if (tid < 16)  sB[tid] = bp[half*16 + tid];
    __syncthreads();

    int tok = blockIdx.x * 256 + tid;
    int b = tok >> 11;
    int t = tok & (TSEQ - 1);
    int nS = (t >> 9) + 1;

    float av[32];
    float lv[4];
#pragma unroll
    for (int i = 0; i < 32; i++) av[i] = 0.f;
#pragma unroll
    for (int h = 0; h < 4; h++) lv[h] = 0.f;

    for (int sI = 0; sI < nS; sI++) {
        size_t base = (((size_t)sI*BSZ + b) * TSEQ + t);
        const float4* ap = (const float4*)&g_Apart[base * NDIM];
#pragma unroll
        for (int i = 0; i < 8; i++) {
            float4 v = ap[i];
            av[4*i] += v.x; av[4*i+1] += v.y; av[4*i+2] += v.z; av[4*i+3] += v.w;
        }
        const float4 lp = *(const float4*)&g_Lpart[base * NH];
        lv[0] += lp.x; lv[1] += lp.y; lv[2] += lp.z; lv[3] += lp.w;
    }

    float zv[32];
#pragma unroll
    for (int h = 0; h < 4; h++) {
        float inv = __frcp_rn(lv[h]);
#pragma unroll
        for (int d = 0; d < 8; d++) zv[h*8+d] = av[h*8+d] * inv;
    }

    float o[16];
#pragma unroll
    for (int d = 0; d < 16; d++) {
        float acc = sB[d];
#pragma unroll
        for (int c = 0; c < 8; c++) {
            float4 w = sW[d*8 + c];
            acc = fmaf(zv[4*c],   w.x,
                  fmaf(zv[4*c+1], w.y,
                  fmaf(zv[4*c+2], w.z,
                  fmaf(zv[4*c+3], w.w, acc))));
        }
        o[d] = acc;
    }
    float4* op = (float4*)&out[(size_t)tok * NDIM + half*16];
#pragma unroll
    for (int c = 0; c < 4; c++)
        op[c] = make_float4(o[4*c], o[4*c+1], o[4*c+2], o[4*c+3]);
}

// ---------------------------------------------------------------------------
extern "C" void kernel_launch(void* const* d_in, const int* in_sizes, int n_in,
                              void* d_out, int out_size)
{
    const float* x  = (const float*)d_in[0];
    const float* Wq = (const float*)d_in[1];
    const float* bq = (const float*)d_in[2];
    const float* Wk = (const float*)d_in[3];
    const float* bk = (const float*)d_in[4];
    const float* Wv = (const float*)d_in[5];
    const float* bv = (const float*)d_in[6];
    const float* Wp = (const float*)d_in[7];
    const float* bp = (const float*)d_in[8];
    float* out = (float*)d_out;

    qkv_kernel<<<(BSZ*TSEQ)/128, 128>>>(x, Wq, bq, Wk, bk, Wv, bv);
    attn_kernel<<<dim3(NS, QB_N, BSZ), 256>>>();
    proj_kernel<<<dim3((BSZ*TSEQ)/256, 2), 256>>>(Wp, bp, out);
}